// round 16
// baseline (speedup 1.0000x reference)
#include <cuda_runtime.h>
#include <cuda_fp16.h>
#include <cstdint>

// Problem constants (fixed by the dataset)
#define NNODES 50000
#define LEV 2
#define RR 2
#define BLK (RR*LEV)          // 4 framelet blocks
#define NNZ 800000
#define F_IN 128
#define F_OUT 64
#define ACT_B (BLK - (LEV-1)) // 3 active blocks (block 0's y is never used)
#define ROWS_T (ACT_B * NNODES)   // 150000 (b, r) rows
#define EDGES_T (ACT_B * NNZ)     // 2400000 active edges
#define NB1 ((ROWS_T + 255) / 256)  // 586 level-1 scan blocks
#define PADDED_E2 (EDGES_T + ROWS_T)  // 2,550,000 (pad-2 worst case)
#define GEMM_BLOCKS (NNODES / 16)     // 3125
#define HIST_BLOCKS ((EDGES_T / 2 + 255) / 256)   // 4688

// ---------------------------------------------------------------------------
// Scratch (champion R15 layout). h, y fp16 (half2-packed): row = 128 B = 8
// uint4. Edge = int2 (col, val-as-fp32-bits) -> no cvt in the SpMMs. Row
// segments padded to even length so int4 loads of 2 edges stay 16B-aligned.
//
// Cross-replay invariant: g_hist == 0 at entry (BSS zero-init for run 1;
// spmm2_csr restores zero after its final read on every replay). This lets
// the fused K1 histogram run with NO zeroing pass.
// ---------------------------------------------------------------------------
__device__ uint4 g_h[(size_t)NNODES * 8];     // 6.4 MB
__device__ uint4 g_y[(size_t)ROWS_T * 8];     // 19.2 MB
__device__ int   g_hist[ROWS_T];              // per-(b,r) nnz (zero on entry!)
__device__ int   g_start[ROWS_T];             // block-local padded excl prefix
__device__ int   g_cursor[ROWS_T];            // scatter cursors (block-local)
__device__ int   g_part[1024];                // scan block partials (exclusive)
__device__ int4  g_ev4[(PADDED_E2 + 1) / 2];  // padded edges, 20.4 MB
#define g_ev ((int2*)g_ev4)

__device__ __forceinline__ unsigned pack_h2(float a, float b) {
    __half2 h = __floats2half2_rn(a, b);
    return *reinterpret_cast<unsigned*>(&h);
}
__device__ __forceinline__ float2 unpack_h2(unsigned u) {
    __half2 h = *reinterpret_cast<__half2*>(&u);
    return __half22float2(h);
}
__device__ __forceinline__ void accum8(float* acc, float v, uint4 hv) {
    const float2 f0 = unpack_h2(hv.x);
    const float2 f1 = unpack_h2(hv.y);
    const float2 f2 = unpack_h2(hv.z);
    const float2 f3 = unpack_h2(hv.w);
    acc[0] += v * f0.x; acc[1] += v * f0.y;
    acc[2] += v * f1.x; acc[3] += v * f1.y;
    acc[4] += v * f2.x; acc[5] += v * f2.y;
    acc[6] += v * f3.x; acc[7] += v * f3.y;
}

// ---------------------------------------------------------------------------
// K1 (role-split): blocks < GEMM_BLOCKS compute h = x @ W (fp32 compute,
// fp16 store); blocks >= GEMM_BLOCKS build the edge histogram (2 edges per
// thread, fire-and-forget REDs). The two roles overlap on the SM array.
// ---------------------------------------------------------------------------
__global__ __launch_bounds__(256) void gemm_hist(const float* __restrict__ x,
                                                 const float* __restrict__ w,
                                                 const int*   __restrict__ rows) {
    const int t = threadIdx.x;

    if (blockIdx.x >= GEMM_BLOCKS) {
        // ---- histogram role ----
        const int p = (blockIdx.x - GEMM_BLOCKS) * 256 + t;
        if (p < EDGES_T / 2) {
            const int2 rp = ((const int2*)(rows + NNZ))[p];
            const int b0 = (2 * p) / NNZ;
            atomicAdd(&g_hist[b0 * NNODES + rp.x], 1);
            atomicAdd(&g_hist[b0 * NNODES + rp.y], 1);
        }
        return;
    }

    // ---- GEMM role ----
    __shared__ float4 ws[F_IN * (F_OUT/4)];   // 32 KB
    __shared__ float4 xs[16 * (F_IN/4)];      // 8 KB

    #pragma unroll
    for (int i = 0; i < 8; i++)
        ws[t + i * 256] = ((const float4*)w)[t + i * 256];

    const size_t row0 = (size_t)blockIdx.x * 16;
    #pragma unroll
    for (int i = 0; i < 2; i++)
        xs[t + i * 256] = ((const float4*)x)[row0 * (F_IN/4) + t + i * 256];

    __syncthreads();

    const int fi = t & 15;
    const int ri = t >> 4;
    float4 acc = make_float4(0.f, 0.f, 0.f, 0.f);

    #pragma unroll
    for (int k = 0; k < F_IN; k += 4) {
        const float4 xv = xs[ri * (F_IN/4) + (k >> 2)];
        const float4 w0 = ws[(k + 0) * 16 + fi];
        const float4 w1 = ws[(k + 1) * 16 + fi];
        const float4 w2 = ws[(k + 2) * 16 + fi];
        const float4 w3 = ws[(k + 3) * 16 + fi];
        acc.x += xv.x * w0.x + xv.y * w1.x + xv.z * w2.x + xv.w * w3.x;
        acc.y += xv.x * w0.y + xv.y * w1.y + xv.z * w2.y + xv.w * w3.y;
        acc.z += xv.x * w0.z + xv.y * w1.z + xv.z * w2.z + xv.w * w3.z;
        acc.w += xv.x * w0.w + xv.y * w1.w + xv.z * w2.w + xv.w * w3.w;
    }
    uint2 p;
    p.x = pack_h2(acc.x, acc.y);
    p.y = pack_h2(acc.z, acc.w);
    ((uint2*)g_h)[(row0 + ri) * 16 + fi] = p;
}

// ---------------------------------------------------------------------------
// scan1: block-local exclusive prefix of PADDED lengths ((len+1)&~1);
// seeds cursors; padded block totals to g_part.
// ---------------------------------------------------------------------------
__global__ __launch_bounds__(256) void scan1() {
    __shared__ int s[256];
    const int t = threadIdx.x;
    const int idx = blockIdx.x * 256 + t;
    const int v  = (idx < ROWS_T) ? g_hist[idx] : 0;
    const int pv = (v + 1) & ~1;             // pad each row to even length
    s[t] = pv;
    __syncthreads();
    #pragma unroll
    for (int off = 1; off < 256; off <<= 1) {
        const int a = (t >= off) ? s[t - off] : 0;
        __syncthreads();
        s[t] += a;
        __syncthreads();
    }
    if (idx < ROWS_T) {
        const int ex = s[t] - pv;
        g_start[idx]  = ex;
        g_cursor[idx] = ex;
    }
    if (t == 255) g_part[blockIdx.x] = s[t];
}

// ---------------------------------------------------------------------------
// scan2: single block exclusive-scans the block totals (guarded: stale
// g_part entries persist across graph replays).
// ---------------------------------------------------------------------------
__global__ __launch_bounds__(1024) void scan2() {
    __shared__ int s[1024];
    const int t = threadIdx.x;
    const int v = (t < NB1) ? g_part[t] : 0;
    s[t] = v;
    __syncthreads();
    #pragma unroll
    for (int off = 1; off < 1024; off <<= 1) {
        const int a = (t >= off) ? s[t - off] : 0;
        __syncthreads();
        s[t] += a;
        __syncthreads();
    }
    if (t < NB1) g_part[t] = s[t] - v;
}

// ---------------------------------------------------------------------------
// Scatter: 2 edges per thread; int2 edge stores (v kept as raw fp32 bits).
// ---------------------------------------------------------------------------
__global__ __launch_bounds__(256) void scatter(const float* __restrict__ vals,
                                               const int*   __restrict__ rows,
                                               const int*   __restrict__ cols) {
    const int p = blockIdx.x * 256 + threadIdx.x;
    if (p >= EDGES_T / 2) return;
    const int2   rp = ((const int2*)(rows + NNZ))[p];
    const int2   cp = ((const int2*)(cols + NNZ))[p];
    const float2 vp = ((const float2*)(vals + NNZ))[p];
    const int base = ((2 * p) / NNZ) * NNODES;

    const int bk0 = base + rp.x;
    const int pos0 = atomicAdd(&g_cursor[bk0], 1) + g_part[bk0 >> 8];
    g_ev[pos0] = make_int2(cp.x, __float_as_int(vp.x));

    const int bk1 = base + rp.y;
    const int pos1 = atomicAdd(&g_cursor[bk1], 1) + g_part[bk1 >> 8];
    g_ev[pos1] = make_int2(cp.y, __float_as_int(vp.y));
}

// ---------------------------------------------------------------------------
// SpMM-1 (CSR gather, 4-edge batched): y[b][r] = filt * sum v_e * h[c_e]
// 8 lanes per row; lane owns one uint4 (8 halves). beg is even -> int4 edge
// loads (2 edges each) are 16B-aligned; 4 feature gathers in flight.
// ---------------------------------------------------------------------------
__global__ __launch_bounds__(256) void spmm1_csr(const float* __restrict__ filt) {
    const int gid = blockIdx.x * 256 + threadIdx.x;
    const int row = gid >> 3;
    if (row >= ROWS_T) return;
    const int q = gid & 7;
    const int beg = g_start[row] + g_part[row >> 8];
    const int len = g_hist[row];
    const int b = row / NNODES;
    const int r = row - b * NNODES;

    float acc[8];
    #pragma unroll
    for (int k = 0; k < 8; k++) acc[k] = 0.f;

    const int2* ev = g_ev + beg;
    int j = 0;
    for (; j + 4 <= len; j += 4) {
        const int4 e01 = *(const int4*)(ev + j);       // (c0,v0,c1,v1)
        const int4 e23 = *(const int4*)(ev + j + 2);   // (c2,v2,c3,v3)
        const uint4 h0 = g_h[(size_t)e01.x * 8 + q];
        const uint4 h1 = g_h[(size_t)e01.z * 8 + q];
        const uint4 h2 = g_h[(size_t)e23.x * 8 + q];
        const uint4 h3 = g_h[(size_t)e23.z * 8 + q];
        accum8(acc, __int_as_float(e01.y), h0);
        accum8(acc, __int_as_float(e01.w), h1);
        accum8(acc, __int_as_float(e23.y), h2);
        accum8(acc, __int_as_float(e23.w), h3);
    }
    for (; j + 2 <= len; j += 2) {
        const int4 e01 = *(const int4*)(ev + j);
        const uint4 h0 = g_h[(size_t)e01.x * 8 + q];
        const uint4 h1 = g_h[(size_t)e01.z * 8 + q];
        accum8(acc, __int_as_float(e01.y), h0);
        accum8(acc, __int_as_float(e01.w), h1);
    }
    for (; j < len; j++) {
        const int2 e = ev[j];
        const uint4 h = g_h[(size_t)e.x * 8 + q];
        accum8(acc, __int_as_float(e.y), h);
    }

    const float f = filt[(size_t)(b + 1) * NNODES + r];
    uint4 o;
    o.x = pack_h2(f * acc[0], f * acc[1]);
    o.y = pack_h2(f * acc[2], f * acc[3]);
    o.z = pack_h2(f * acc[4], f * acc[5]);
    o.w = pack_h2(f * acc[6], f * acc[7]);
    g_y[(size_t)row * 8 + q] = o;
}

// ---------------------------------------------------------------------------
// SpMM-2 (CSR gather, 4-edge batched): out[r] = bias + sum_b sum v_e * y[b][c]
// Restores g_hist = 0 after its final read (warp-local slot: the warp-wide
// LDG precedes lane-0's STG in program order; no other warp reads the slot).
// ---------------------------------------------------------------------------
__global__ __launch_bounds__(256) void spmm2_csr(float* __restrict__ out,
                                                 const float* __restrict__ bias) {
    const int gid = blockIdx.x * 256 + threadIdx.x;
    const int r = gid >> 3;
    if (r >= NNODES) return;
    const int q = gid & 7;

    float acc[8];
    {
        const float4 b0 = ((const float4*)bias)[q * 2 + 0];
        const float4 b1 = ((const float4*)bias)[q * 2 + 1];
        acc[0] = b0.x; acc[1] = b0.y; acc[2] = b0.z; acc[3] = b0.w;
        acc[4] = b1.x; acc[5] = b1.y; acc[6] = b1.z; acc[7] = b1.w;
    }

    #pragma unroll
    for (int b = 0; b < ACT_B; b++) {
        const int row = b * NNODES + r;
        const int beg = g_start[row] + g_part[row >> 8];
        const int len = g_hist[row];
        if (q == 0) g_hist[row] = 0;     // restore invariant for next replay
        const size_t ybase = (size_t)b * NNODES * 8;
        const int2* ev = g_ev + beg;
        int j = 0;
        for (; j + 4 <= len; j += 4) {
            const int4 e01 = *(const int4*)(ev + j);
            const int4 e23 = *(const int4*)(ev + j + 2);
            const uint4 y0 = g_y[ybase + (size_t)e01.x * 8 + q];
            const uint4 y1 = g_y[ybase + (size_t)e01.z * 8 + q];
            const uint4 y2 = g_y[ybase + (size_t)e23.x * 8 + q];
            const uint4 y3 = g_y[ybase + (size_t)e23.z * 8 + q];
            accum8(acc, __int_as_float(e01.y), y0);
            accum8(acc, __int_as_float(e01.w), y1);
            accum8(acc, __int_as_float(e23.y), y2);
            accum8(acc, __int_as_float(e23.w), y3);
        }
        for (; j + 2 <= len; j += 2) {
            const int4 e01 = *(const int4*)(ev + j);
            const uint4 y0 = g_y[ybase + (size_t)e01.x * 8 + q];
            const uint4 y1 = g_y[ybase + (size_t)e01.z * 8 + q];
            accum8(acc, __int_as_float(e01.y), y0);
            accum8(acc, __int_as_float(e01.w), y1);
        }
        for (; j < len; j++) {
            const int2 e = ev[j];
            const uint4 yv = g_y[ybase + (size_t)e.x * 8 + q];
            accum8(acc, __int_as_float(e.y), yv);
        }
    }
    float4* op = (float4*)(out + (size_t)r * F_OUT + q * 8);
    op[0] = make_float4(acc[0], acc[1], acc[2], acc[3]);
    op[1] = make_float4(acc[4], acc[5], acc[6], acc[7]);
}

// ---------------------------------------------------------------------------
// Launch: K1(gemm||hist), scan1, scan2, scatter, spmm1, spmm2(+restore)
// ---------------------------------------------------------------------------
extern "C" void kernel_launch(void* const* d_in, const int* in_sizes, int n_in,
                              void* d_out, int out_size) {
    const float* x    = (const float*)d_in[0];
    const float* wgt  = (const float*)d_in[1];
    const float* filt = (const float*)d_in[2];
    const float* bias = (const float*)d_in[3];
    const float* vals = (const float*)d_in[4];
    const int*   rows = (const int*)d_in[5];
    const int*   cols = (const int*)d_in[6];
    float* out = (float*)d_out;

    gemm_hist<<<GEMM_BLOCKS + HIST_BLOCKS, 256>>>(x, wgt, rows);   // #1
    scan1<<<NB1, 256>>>();                                         // #2
    scan2<<<1, 1024>>>();                                          // #3
    scatter<<<(EDGES_T / 2 + 255) / 256, 256>>>(vals, rows, cols); // #4
    spmm1_csr<<<(ROWS_T * 8 + 255) / 256, 256>>>(filt);            // #5
    spmm2_csr<<<(NNODES * 8 + 255) / 256, 256>>>(out, bias);       // #6
}